// round 10
// baseline (speedup 1.0000x reference)
#include <cuda_runtime.h>

// ---------------- static problem sizes ----------------
#define N_NODES 20000
#define E_EDGES 320000
#define B_Q 4
#define K_T 32
#define D_DIM 32
#define DR_REL 40
#define T_STEPS 10
#define VTH 2.0f
#define DECAY 0.7788007830714049f   // exp(-1/4)
#define RATIO 0.95f
#define NSCALE 8.025261215232422f   // (1 - 0.95^10) / (1 - 0.95)

#define NTHR 256
#define NW 8                         // warps per block

// ---------------- persistent state (zero-init; cleanup restores zeros) ----------------
// Fast path touches NONE of these.
__device__ unsigned g_smask[T_STEPS * N_NODES * B_Q];
__device__ float    g_v[N_NODES * B_Q * D_DIM];
__device__ float    g_c[N_NODES * B_Q * D_DIM];
__device__ float    g_agg[N_NODES * B_Q * D_DIM];
__device__ int      g_hot_flag[N_NODES];
__device__ int      g_hot_list[N_NODES];
__device__ float    g_wrel[B_Q * DR_REL * D_DIM];

__global__ __launch_bounds__(NTHR, 1)
void fused_kernel(const int* __restrict__ edge_src,
                  const int* __restrict__ edge_dst,
                  const int* __restrict__ edge_type,
                  const int* __restrict__ h_index,
                  const int* __restrict__ t_index,
                  const int* __restrict__ r_index,
                  const float* __restrict__ query_emb,
                  const float* __restrict__ relw_W,
                  const float* __restrict__ relw_b,
                  const float* __restrict__ lin_W,
                  const float* __restrict__ lin_b,
                  const float* __restrict__ W1,
                  const float* __restrict__ b1,
                  const float* __restrict__ W2,
                  const float* __restrict__ b2,
                  float* __restrict__ out) {
    __shared__ float s_qe[DR_REL * D_DIM];   // full query_emb table (5 KB)
    __shared__ float s_W1[64 * 65];          // padded row-major W1
    __shared__ float s_WT[D_DIM * D_DIM];    // lin_W^T (slow path only)
    __shared__ float s_q[B_Q * D_DIM];
    __shared__ float s_b1[64], s_W2[64];
    __shared__ float s_score[B_Q];
    __shared__ float s_b2s;
    __shared__ int   s_r[B_Q];
    __shared__ int   s_ts, s_hot, s_fprev, s_fcur, s_wrel_done;

    const int tid  = threadIdx.x;
    const int lane = tid & 31;
    const int warp = tid >> 5;

    // ---------- one parallel load round: everything the fast path needs ----------
    {   // query_emb table: 320 float4
        const float4* qe4 = reinterpret_cast<const float4*>(query_emb);
        float4* sqe4 = reinterpret_cast<float4*>(s_qe);
        for (int i = tid; i < (DR_REL * D_DIM) / 4; i += NTHR)
            sqe4[i] = __ldg(qe4 + i);
    }
    {   // W1 columns 32..63 only (the half the fast path uses): row j, elems 32..63
        const float4* W14 = reinterpret_cast<const float4*>(W1);
#pragma unroll
        for (int q = 0; q < 2; ++q) {
            int k = q * NTHR + tid;             // 0..511 : (row j = k>>3, quad = k&7)
            int j = k >> 3, qd = (k & 7) + 8;   // quads 8..15 = elems 32..63
            float4 v = __ldg(W14 + j * 16 + qd);
            float* dst = s_W1 + j * 65 + (qd << 2);
            dst[0] = v.x; dst[1] = v.y; dst[2] = v.z; dst[3] = v.w;
        }
    }
    if (tid < B_Q) s_r[tid] = __ldg(r_index + tid);
    if (tid < 64) { s_b1[tid] = __ldg(b1 + tid); s_W2[tid] = __ldg(W2 + tid); }
    if (tid == 0) {
        s_b2s = __ldg(b2);
        s_ts = T_STEPS; s_hot = 0; s_fprev = 0; s_fcur = 0; s_wrel_done = 0;
    }
    __syncthreads();

    if (tid < B_Q * D_DIM)
        s_q[tid] = s_qe[s_r[tid >> 5] * D_DIM + (tid & 31)];
    __syncthreads();

    // ---------- first-spike scan: before any spike c == 0, so v decays strictly;
    //            a spike is only possible at t = 0 ----------
    if (warp < B_Q) {
        float q = s_q[warp * D_DIM + lane];
        float boundary = q * (VTH * 0.5f) + VTH * 0.5f;
        unsigned m0 = __ballot_sync(0xffffffffu, (boundary - VTH) >= 0.f);
        if (lane == 0 && m0) s_ts = 0;       // only value ever written is 0
    }
    __syncthreads();
    const int ts = s_ts;

    // ======================= FAST PATH: no spikes ever =======================
    if (ts == T_STEPS) {
        // 4 distinct scores (enc == 0; feat = [0, query_b]); enc-half of W1 unused.
        if (warp < B_Q) {
            float f1 = s_q[warp * D_DIM + lane];
            float acc0 = s_b1[lane], acc1 = s_b1[lane + 32];
#pragma unroll
            for (int i = 0; i < 32; ++i) {
                float c = __shfl_sync(0xffffffffu, f1, i);
                acc0 = fmaf(c, s_W1[lane * 65 + 32 + i],        acc0);
                acc1 = fmaf(c, s_W1[(lane + 32) * 65 + 32 + i], acc1);
            }
            float h = fmaxf(acc0, 0.f) * s_W2[lane] + fmaxf(acc1, 0.f) * s_W2[lane + 32];
#pragma unroll
            for (int off = 16; off; off >>= 1)
                h += __shfl_down_sync(0xffffffffu, h, off);
            if (lane == 0) s_score[warp] = h + s_b2s;
        }
        __syncthreads();
        if (tid < B_Q * K_T) out[tid] = s_score[tid >> 5];
        return;
    }

    // ======================= SLOW PATH (spikes exist; single-block generic) =======================
    // load the other half of W1 (columns 0..31) for the full-feature score
    {
        const float4* W14 = reinterpret_cast<const float4*>(W1);
#pragma unroll
        for (int q = 0; q < 2; ++q) {
            int k = q * NTHR + tid;
            int j = k >> 3, qd = k & 7;          // quads 0..7 = elems 0..31
            float4 v = __ldg(W14 + j * 16 + qd);
            float* dst = s_W1 + j * 65 + (qd << 2);
            dst[0] = v.x; dst[1] = v.y; dst[2] = v.z; dst[3] = v.w;
        }
    }
    // materialize head-node state at ts
    if (warp < B_Q) {
        int b = warp;
        int n = __ldg(h_index + b);
        float q = s_q[b * D_DIM + lane];
        float boundary = q * (VTH * 0.5f) + VTH * 0.5f;
        float v = boundary, c = 0.f;
        for (int t = 1; t <= ts; ++t) { c *= DECAY; v = v * DECAY + c; }
        bool sp = (v - VTH) >= 0.f;
        unsigned bm = __ballot_sync(0xffffffffu, sp);
        if (sp) v = 0.f;
        size_t base = (size_t)(n * B_Q + b) * D_DIM + lane;
        g_v[base] = v;
        g_c[base] = c;
        if (lane == 0) {
            if (bm) {
                g_smask[(size_t)ts * (N_NODES * B_Q) + n * B_Q + b] = bm;
                atomicAdd(&s_fprev, 1);
            }
            if (atomicExch(&g_hot_flag[n], 1) == 0) {
                int p = atomicAdd(&s_hot, 1);
                g_hot_list[p] = n;
            }
        }
    }
    for (int i = tid; i < D_DIM * D_DIM; i += NTHR) {
        int ii = i >> 5, j = i & 31;
        s_WT[i] = lin_W[j * D_DIM + ii];
    }
    __syncthreads();

    const float lb = __ldg(lin_b + lane);
    for (int t = ts + 1; t < T_STEPS; ++t) {
        int fc = s_fprev;
        if (fc != 0) {
            if (!s_wrel_done) {
                for (int id = tid; id < B_Q * DR_REL * D_DIM; id += NTHR) {
                    int b  = id / (DR_REL * D_DIM);
                    int rd = id % (DR_REL * D_DIM);
                    float acc = relw_b[rd];
#pragma unroll
                    for (int i = 0; i < D_DIM; ++i)
                        acc += s_q[b * D_DIM + i] * relw_W[i * (DR_REL * D_DIM) + rd];
                    g_wrel[id] = acc;
                }
                __syncthreads();
                if (tid == 0) s_wrel_done = 1;
            }
            const unsigned* mp = g_smask + (size_t)(t - 1) * (N_NODES * B_Q);
            for (int e = warp; e < E_EDGES; e += NW) {
                int src = __ldg(edge_src + e);
                uint4 m = *reinterpret_cast<const uint4*>(mp + src * 4);
                if (m.x | m.y | m.z | m.w) {
                    int dst = __ldg(edge_dst + e);
                    int ty  = __ldg(edge_type + e);
                    if (lane == 0) {
                        if (atomicExch(&g_hot_flag[dst], 1) == 0) {
                            int p = atomicAdd(&s_hot, 1);
                            g_hot_list[p] = dst;
                        }
                    }
                    int off = ty * D_DIM + lane;
                    float* ag = g_agg + (size_t)(dst * B_Q) * D_DIM + lane;
                    if ((m.x >> lane) & 1u) atomicAdd(ag + 0 * D_DIM, g_wrel[0 * DR_REL * D_DIM + off]);
                    if ((m.y >> lane) & 1u) atomicAdd(ag + 1 * D_DIM, g_wrel[1 * DR_REL * D_DIM + off]);
                    if ((m.z >> lane) & 1u) atomicAdd(ag + 2 * D_DIM, g_wrel[2 * DR_REL * D_DIM + off]);
                    if ((m.w >> lane) & 1u) atomicAdd(ag + 3 * D_DIM, g_wrel[3 * DR_REL * D_DIM + off]);
                }
            }
            __syncthreads();
        }
        int nh = s_hot;
        for (int i = warp; i < nh; i += NW) {
            int n = g_hot_list[i];
            size_t base = (size_t)(n * B_Q) * D_DIM + lane;
            float a0 = 0.f, a1 = 0.f, a2 = 0.f, a3 = 0.f;
            if (fc != 0) {
                a0 = g_agg[base + 0 * D_DIM]; g_agg[base + 0 * D_DIM] = 0.f;
                a1 = g_agg[base + 1 * D_DIM]; g_agg[base + 1 * D_DIM] = 0.f;
                a2 = g_agg[base + 2 * D_DIM]; g_agg[base + 2 * D_DIM] = 0.f;
                a3 = g_agg[base + 3 * D_DIM]; g_agg[base + 3 * D_DIM] = 0.f;
            }
            float x0 = lb, x1 = lb, x2 = lb, x3 = lb;
#pragma unroll
            for (int k = 0; k < D_DIM; ++k) {
                float w = s_WT[k * D_DIM + lane];
                x0 = fmaf(__shfl_sync(0xffffffffu, a0, k), w, x0);
                x1 = fmaf(__shfl_sync(0xffffffffu, a1, k), w, x1);
                x2 = fmaf(__shfl_sync(0xffffffffu, a2, k), w, x2);
                x3 = fmaf(__shfl_sync(0xffffffffu, a3, k), w, x3);
            }
            unsigned bm[4];
            float xs[4] = {x0, x1, x2, x3};
#pragma unroll
            for (int b = 0; b < B_Q; ++b) {
                float c = g_c[base + b * D_DIM] * DECAY + xs[b];
                float v = g_v[base + b * D_DIM] * DECAY + c;
                bool sp = (v - VTH) >= 0.f;
                g_c[base + b * D_DIM] = c;
                g_v[base + b * D_DIM] = sp ? 0.f : v;
                bm[b] = __ballot_sync(0xffffffffu, sp);
            }
            if (lane == 0) {
                *reinterpret_cast<uint4*>(g_smask + (size_t)t * (N_NODES * B_Q) + n * B_Q) =
                    make_uint4(bm[0], bm[1], bm[2], bm[3]);
                if (bm[0] | bm[1] | bm[2] | bm[3]) atomicAdd(&s_fcur, 1);
            }
        }
        __syncthreads();
        if (tid == 0) { s_fprev = s_fcur; s_fcur = 0; }
        __syncthreads();
    }

    // full score: warp per (b,k), 16 rounds over 128 pairs
    for (int p = warp; p < B_Q * K_T; p += NW) {
        int b = p >> 5;                      // K_T == 32
        int tn = __ldg(t_index + p);
        float e = 0.f, w = 1.0f;
#pragma unroll
        for (int t = 0; t < T_STEPS; ++t) {
            unsigned m = g_smask[(size_t)t * (N_NODES * B_Q) + tn * B_Q + b];
            if ((m >> lane) & 1u) e += w;
            w *= RATIO;
        }
        float f0 = e / NSCALE;
        float f1 = s_q[b * D_DIM + lane];
        float acc0 = s_b1[lane], acc1 = s_b1[lane + 32];
#pragma unroll
        for (int i = 0; i < 32; ++i) {
            float a = __shfl_sync(0xffffffffu, f0, i);
            float c = __shfl_sync(0xffffffffu, f1, i);
            acc0 = fmaf(a, s_W1[lane * 65 + i],              acc0);
            acc0 = fmaf(c, s_W1[lane * 65 + 32 + i],         acc0);
            acc1 = fmaf(a, s_W1[(lane + 32) * 65 + i],       acc1);
            acc1 = fmaf(c, s_W1[(lane + 32) * 65 + 32 + i],  acc1);
        }
        float h = fmaxf(acc0, 0.f) * s_W2[lane] + fmaxf(acc1, 0.f) * s_W2[lane + 32];
#pragma unroll
        for (int off = 16; off; off >>= 1)
            h += __shfl_down_sync(0xffffffffu, h, off);
        if (lane == 0) out[p] = h + s_b2s;
    }
    __syncthreads();

    // cleanup: restore pristine zeros for next replay
    {
        int nh = s_hot;
        for (int i = warp; i < nh; i += NW) {
            int n = g_hot_list[i];
            size_t base = (size_t)(n * B_Q) * D_DIM + lane;
#pragma unroll
            for (int b = 0; b < B_Q; ++b) {
                g_v[base + b * D_DIM]   = 0.f;
                g_c[base + b * D_DIM]   = 0.f;
                g_agg[base + b * D_DIM] = 0.f;
            }
            if (lane < T_STEPS)
                *reinterpret_cast<uint4*>(g_smask + (size_t)lane * (N_NODES * B_Q) + n * B_Q) =
                    make_uint4(0u, 0u, 0u, 0u);
            if (lane == 0) g_hot_flag[n] = 0;
        }
    }
}

// ---------------- launch ----------------
extern "C" void kernel_launch(void* const* d_in, const int* in_sizes, int n_in,
                              void* d_out, int out_size) {
    fused_kernel<<<1, NTHR>>>(
        (const int*)d_in[0], (const int*)d_in[1], (const int*)d_in[2],
        (const int*)d_in[3], (const int*)d_in[4], (const int*)d_in[5],
        (const float*)d_in[6], (const float*)d_in[7], (const float*)d_in[8],
        (const float*)d_in[9], (const float*)d_in[10],
        (const float*)d_in[11], (const float*)d_in[12],
        (const float*)d_in[13], (const float*)d_in[14],
        (float*)d_out);
}